// round 3
// baseline (speedup 1.0000x reference)
#include <cuda_runtime.h>
#include <cstdint>

// ---------------------------------------------------------------------------
// EdgeUpdate: fused gather + MLP(relu) + per-edge tensor-product contraction
// + residual + LayerNorm.  tf32 mma.sync path, W2 streamed from L2, never
// materializing the (E,5120) intermediate.
// Round 2 fix: edge_index is int32 (JAX x64-disabled downcasts jnp.int64).
// ---------------------------------------------------------------------------

constexpr int H_STR  = 140;            // Hs row stride (136 cols used + pad)
constexpr int W2_STR = 72;             // W2 chunk row stride (64 cols + pad)
constexpr int F_STR  = 81;             // feats row stride (80 + pad)

constexpr int HS_SZ   = 128 * H_STR;           // 17920 floats
constexpr int W2_SZ   = 136 * W2_STR;          // 9792 floats per buffer
constexpr int FS_OFF  = HS_SZ + 2 * W2_SZ;     // 37504
constexpr int FS_SZ   = 128 * F_STR;           // 10368
constexpr int B1_OFF  = FS_OFF + FS_SZ;        // 47872
constexpr int GB_OFF  = B1_OFF + 128;          // 48000
constexpr int SMEM_FLOATS = GB_OFF + 128;      // 48128 -> 192512 bytes

__device__ __forceinline__ unsigned cvt_tf32(float x) {
    unsigned r;
    asm("cvt.rna.tf32.f32 %0, %1;" : "=r"(r) : "f"(x));
    return r;
}

__device__ __forceinline__ void mma_tf32(float* c, const unsigned* a, const unsigned* b) {
    asm volatile(
        "mma.sync.aligned.m16n8k8.row.col.f32.tf32.tf32.f32 "
        "{%0,%1,%2,%3}, {%4,%5,%6,%7}, {%8,%9}, {%0,%1,%2,%3};"
        : "+f"(c[0]), "+f"(c[1]), "+f"(c[2]), "+f"(c[3])
        : "r"(a[0]), "r"(a[1]), "r"(a[2]), "r"(a[3]), "r"(b[0]), "r"(b[1]));
}

__device__ __forceinline__ void cp_async16(float* smem_dst, const float* gsrc) {
    unsigned saddr = (unsigned)__cvta_generic_to_shared(smem_dst);
    asm volatile("cp.async.cg.shared.global [%0], [%1], 16;" :: "r"(saddr), "l"(gsrc));
}

__global__ __launch_bounds__(128, 1)
void edge_kernel(const float* __restrict__ res,
                 const float* __restrict__ xf,
                 const float* __restrict__ esh,
                 const float* __restrict__ W1,
                 const float* __restrict__ b1,
                 const float* __restrict__ W2,
                 const float* __restrict__ b2,
                 const float* __restrict__ gamma,
                 const float* __restrict__ beta,
                 const int* __restrict__ ei,
                 float* __restrict__ out,
                 int E)
{
    extern __shared__ float smem[];
    const int tid  = threadIdx.x;
    const int lane = tid & 31;
    const int w    = tid >> 5;       // warp 0..3
    const int g    = lane >> 2;      // groupID 0..7
    const int q    = lane & 3;       // threadID_in_group 0..3
    const int e0   = blockIdx.x * 128;

    float* Hs   = smem;
    float* W2s0 = smem + HS_SZ;
    float* fs   = smem + FS_OFF;
    float* b1s  = smem + B1_OFF;
    float* gs   = smem + GB_OFF;
    float* bs   = gs + 64;

    // ---------------- phase 0: stage W1 / X / b1 / gamma / beta -----------
    float* W1s = W2s0;               // 8192 floats (aliased into W2 buffers)
    float* Xs  = W2s0 + 8192;        // 128 x 65   (aliased)
    for (int idx = tid; idx < 8192; idx += 128) {
        W1s[idx] = W1[idx];
        int r = idx >> 6, c = idx & 63;
        Xs[r * 65 + c] = xf[(size_t)(e0 + r) * 64 + c];
    }
    b1s[tid] = b1[tid];
    if (tid < 64) { gs[tid] = gamma[tid]; bs[tid] = beta[tid]; }

    // ---------------- feats gather (one edge per thread) -------------------
    {
        const int e = e0 + tid;
        const int di = ei[e];            // dst = res[edge_index[0]]
        const int si = ei[E + e];        // src = res[edge_index[1]]
        const float* sr = res + (size_t)si * 56;
        const float* dr = res + (size_t)di * 56;
        const float s0 = esh[e * 4 + 0];
        const float sx = esh[e * 4 + 1];
        const float sy = esh[e * 4 + 2];
        const float sz = esh[e * 4 + 3];
        float* fr = fs + tid * F_STR;
        #pragma unroll
        for (int j = 0; j < 32; j++) { fr[j] = sr[j] * s0; fr[32 + j] = dr[j] * s0; }
        const float inv3 = 0.57735026918962576f;   // 1/sqrt(3)
        #pragma unroll
        for (int m = 0; m < 8; m++) {
            fr[64 + m] = (sr[32 + 3*m] * sx + sr[33 + 3*m] * sy + sr[34 + 3*m] * sz) * inv3;
            fr[72 + m] = (dr[32 + 3*m] * sx + dr[33 + 3*m] * sy + dr[34 + 3*m] * sz) * inv3;
        }
    }
    __syncthreads();

    // ---------------- phase 1: H = relu(X @ W1 + b1), one row per thread ---
    {
        const int e = tid;
        float* hrow = Hs + e * H_STR;
        #pragma unroll 1
        for (int jb = 0; jb < 4; jb++) {
            float acc[32];
            #pragma unroll
            for (int jj = 0; jj < 32; jj++) acc[jj] = b1s[jb * 32 + jj];
            #pragma unroll 4
            for (int i = 0; i < 64; i++) {
                const float xv = Xs[e * 65 + i];
                const float* wrow = W1s + i * 128 + jb * 32;
                #pragma unroll
                for (int jj = 0; jj < 32; jj++) acc[jj] = fmaf(xv, wrow[jj], acc[jj]);
            }
            #pragma unroll
            for (int jj = 0; jj < 32; jj++) hrow[jb * 32 + jj] = fmaxf(acc[jj], 0.f);
        }
        hrow[128] = 1.0f;                      // augmented column for b2
        #pragma unroll
        for (int c = 129; c < 136; c++) hrow[c] = 0.f;
    }
    __syncthreads();   // Xs / W1s dead from here; W2 buffers take over

    // zero K-padding rows (129..135) of both W2 chunk buffers
    for (int idx = tid; idx < 7 * W2_STR * 2; idx += 128) {
        int bsel = idx / (7 * W2_STR);
        int rr   = idx % (7 * W2_STR);
        W2s0[bsel * W2_SZ + 129 * W2_STR + rr] = 0.f;
    }

    // ---------------- main loop: 80 d-chunks of W2 -------------------------
    auto prefetch = [&](int d, int buf) {
        float* dstb = W2s0 + buf * W2_SZ;
        const float* src_base = W2 + (size_t)d * 64;
        #pragma unroll 4
        for (int c = tid; c < 128 * 16; c += 128) {
            int k = c >> 4, seg = c & 15;
            cp_async16(dstb + k * W2_STR + seg * 4, src_base + (size_t)k * 5120 + seg * 4);
        }
        if (tid < 16) cp_async16(dstb + 128 * W2_STR + tid * 4, b2 + (size_t)d * 64 + tid * 4);
        asm volatile("cp.async.commit_group;");
    };

    prefetch(0, 0);

    float acc[2][8][4];
    #pragma unroll
    for (int mt = 0; mt < 2; mt++)
        #pragma unroll
        for (int nt = 0; nt < 8; nt++)
            #pragma unroll
            for (int i = 0; i < 4; i++) acc[mt][nt][i] = 0.f;

    const int rowA0 = w * 32 + g;   // a0/a2 row of m-tile 0

    #pragma unroll 1
    for (int d = 0; d < 80; d++) {
        const int buf = d & 1;
        if (d + 1 < 80) {
            prefetch(d + 1, buf ^ 1);
            asm volatile("cp.async.wait_group 1;");
        } else {
            asm volatile("cp.async.wait_group 0;");
        }
        __syncthreads();

        const float* Wb = W2s0 + buf * W2_SZ;
        const float f00 = fs[(rowA0)      * F_STR + d];
        const float f01 = fs[(rowA0 + 8)  * F_STR + d];
        const float f10 = fs[(rowA0 + 16) * F_STR + d];
        const float f11 = fs[(rowA0 + 24) * F_STR + d];

        #pragma unroll 1
        for (int kt = 0; kt < 17; kt++) {
            const int k0 = kt * 8 + q;
            const float* h0 = Hs + (rowA0)      * H_STR + k0;
            const float* h1 = Hs + (rowA0 + 8)  * H_STR + k0;
            const float* h2 = Hs + (rowA0 + 16) * H_STR + k0;
            const float* h3 = Hs + (rowA0 + 24) * H_STR + k0;
            unsigned a0[4], a1[4];
            a0[0] = cvt_tf32(h0[0] * f00); a0[1] = cvt_tf32(h1[0] * f01);
            a0[2] = cvt_tf32(h0[4] * f00); a0[3] = cvt_tf32(h1[4] * f01);
            a1[0] = cvt_tf32(h2[0] * f10); a1[1] = cvt_tf32(h3[0] * f11);
            a1[2] = cvt_tf32(h2[4] * f10); a1[3] = cvt_tf32(h3[4] * f11);
            const float* wk0 = Wb + (size_t)k0 * W2_STR;        // b0 rows (k)
            const float* wk1 = Wb + (size_t)(k0 + 4) * W2_STR;  // b1 rows (k+4)
            #pragma unroll
            for (int nt = 0; nt < 8; nt++) {
                unsigned b[2];
                b[0] = cvt_tf32(wk0[nt * 8 + g]);
                b[1] = cvt_tf32(wk1[nt * 8 + g]);
                mma_tf32(acc[0][nt], a0, b);
                mma_tf32(acc[1][nt], a1, b);
            }
        }
        __syncthreads();   // protect buf^1 before next prefetch overwrites it
    }

    // ---------------- epilogue: residual + LayerNorm ------------------------
    const float inv_s80 = 0.111803398874989485f;   // 1/sqrt(80)
    #pragma unroll
    for (int mt = 0; mt < 2; mt++) {
        #pragma unroll
        for (int par = 0; par < 2; par++) {
            const int r = rowA0 + mt * 16 + par * 8;
            const size_t rg = (size_t)(e0 + r);
            const float* xrow = xf + rg * 64;
            float v[16];
            float s = 0.f, ss = 0.f;
            #pragma unroll
            for (int nt = 0; nt < 8; nt++) {
                const int h = nt * 8 + 2 * q;
                const float2 xv = *(const float2*)(xrow + h);
                const float v0 = acc[mt][nt][par * 2 + 0] * inv_s80 + xv.x;
                const float v1 = acc[mt][nt][par * 2 + 1] * inv_s80 + xv.y;
                v[nt * 2] = v0; v[nt * 2 + 1] = v1;
                s += v0 + v1;
                ss += v0 * v0 + v1 * v1;
            }
            s  += __shfl_xor_sync(0xffffffffu, s, 1);
            s  += __shfl_xor_sync(0xffffffffu, s, 2);
            ss += __shfl_xor_sync(0xffffffffu, ss, 1);
            ss += __shfl_xor_sync(0xffffffffu, ss, 2);
            const float mean = s * (1.f / 64.f);
            const float var  = ss * (1.f / 64.f) - mean * mean;
            const float rstd = rsqrtf(var + 1e-5f);
            float* orow = out + rg * 64;
            #pragma unroll
            for (int nt = 0; nt < 8; nt++) {
                const int h = nt * 8 + 2 * q;
                float2 o;
                o.x = (v[nt * 2]     - mean) * rstd * gs[h]     + bs[h];
                o.y = (v[nt * 2 + 1] - mean) * rstd * gs[h + 1] + bs[h + 1];
                *(float2*)(orow + h) = o;
            }
        }
    }
}

extern "C" void kernel_launch(void* const* d_in, const int* in_sizes, int n_in,
                              void* d_out, int out_size)
{
    const float* res   = (const float*)d_in[0];
    const float* xf    = (const float*)d_in[1];
    const float* esh   = (const float*)d_in[2];
    const float* W1    = (const float*)d_in[3];
    const float* b1    = (const float*)d_in[4];
    const float* W2    = (const float*)d_in[5];
    const float* b2    = (const float*)d_in[6];
    const float* gamma = (const float*)d_in[7];
    const float* beta  = (const float*)d_in[8];
    const int*   ei    = (const int*)d_in[9];   // int32: JAX x64-disabled

    const int E = in_sizes[1] / 64;            // edge_features is (E, 64)
    const size_t smem_bytes = SMEM_FLOATS * sizeof(float);

    cudaFuncSetAttribute(edge_kernel, cudaFuncAttributeMaxDynamicSharedMemorySize,
                         (int)smem_bytes);

    edge_kernel<<<E / 128, 128, smem_bytes>>>(res, xf, esh, W1, b1, W2, b2,
                                              gamma, beta, ei, (float*)d_out, E);
}

// round 5
// speedup vs baseline: 1.4778x; 1.4778x over previous
#include <cuda_runtime.h>
#include <cstdint>

// ---------------------------------------------------------------------------
// EdgeUpdate: fused gather + MLP(relu) + per-edge tensor-product contraction
// + residual + LayerNorm.  tf32 mma.sync, W2 streamed from L2.
// R3: 256 threads (2 warps/SMSP, kt-split warp pairs), pre-rounded W2 (no B
// cvt), rounded-H + truncated-A fragments (no inner-loop cvt), LDS.64 A loads.
// ---------------------------------------------------------------------------

constexpr int H_STR  = 140;            // Hs row stride (4 groups * 34 + pad)
constexpr int W2_STR = 72;             // W2 chunk row stride (64 cols + pad)
constexpr int F_STR  = 81;             // feats row stride (80 + pad)

constexpr int HS_SZ   = 128 * H_STR;           // 17920 floats
constexpr int W2_SZ   = 136 * W2_STR;          // 9792 floats per buffer
constexpr int FS_OFF  = HS_SZ + 2 * W2_SZ;     // 37504
constexpr int FS_SZ   = 128 * F_STR;           // 10368
constexpr int B1_OFF  = FS_OFF + FS_SZ;        // 47872
constexpr int GB_OFF  = B1_OFF + 128;          // 48000
constexpr int SMEM_FLOATS = GB_OFF + 128;      // 48128 -> 192512 bytes

// tf32-rounded copies of W2 / b2 (written once by round_w2 pre-pass kernel)
__device__ float w2r[128 * 5120];
__device__ float b2r[5120];

__device__ __forceinline__ unsigned cvt_tf32(float x) {
    unsigned r;
    asm("cvt.rna.tf32.f32 %0, %1;" : "=r"(r) : "f"(x));
    return r;
}

__device__ __forceinline__ void mma_tf32(float* c, const unsigned* a, const unsigned* b) {
    asm volatile(
        "mma.sync.aligned.m16n8k8.row.col.f32.tf32.tf32.f32 "
        "{%0,%1,%2,%3}, {%4,%5,%6,%7}, {%8,%9}, {%0,%1,%2,%3};"
        : "+f"(c[0]), "+f"(c[1]), "+f"(c[2]), "+f"(c[3])
        : "r"(a[0]), "r"(a[1]), "r"(a[2]), "r"(a[3]), "r"(b[0]), "r"(b[1]));
}

__device__ __forceinline__ void cp_async16(float* smem_dst, const float* gsrc) {
    unsigned saddr = (unsigned)__cvta_generic_to_shared(smem_dst);
    asm volatile("cp.async.cg.shared.global [%0], [%1], 16;" :: "r"(saddr), "l"(gsrc));
}

__global__ void round_w2(const float* __restrict__ W2, const float* __restrict__ b2) {
    const int i = blockIdx.x * 256 + threadIdx.x;
    if (i < 128 * 5120) w2r[i] = __uint_as_float(cvt_tf32(W2[i]));
    if (i < 5120)       b2r[i] = __uint_as_float(cvt_tf32(b2[i]));
}

__global__ __launch_bounds__(256, 1)
void edge_kernel(const float* __restrict__ res,
                 const float* __restrict__ xf,
                 const float* __restrict__ esh,
                 const float* __restrict__ W1,
                 const float* __restrict__ b1,
                 const float* __restrict__ gamma,
                 const float* __restrict__ beta,
                 const int* __restrict__ ei,
                 float* __restrict__ out,
                 int E)
{
    extern __shared__ float smem[];
    const int tid   = threadIdx.x;
    const int lane  = tid & 31;
    const int w     = tid >> 5;        // warp 0..7
    const int wp    = w >> 1;          // warp-pair 0..3 (shares 32 M-rows)
    const int kh    = w & 1;           // kt-range half
    const int g     = lane >> 2;       // groupID 0..7
    const int q     = lane & 3;        // threadID_in_group 0..3
    const int e0    = blockIdx.x * 128;

    float* Hs   = smem;
    float* W2s0 = smem + HS_SZ;
    float* fs   = smem + FS_OFF;
    float* b1s  = smem + B1_OFF;
    float* gs   = smem + GB_OFF;
    float* bs   = gs + 64;

    // ---------------- phase 0: stage W1 / X / b1 / gamma / beta ------------
    float* W1s = W2s0;                 // 8192 floats (aliased into W2 buffers)
    float* Xs  = W2s0 + 8192;          // 128 x 65   (aliased)
    for (int idx = tid; idx < 8192; idx += 256) {
        W1s[idx] = W1[idx];
        int r = idx >> 6, c = idx & 63;
        Xs[r * 65 + c] = xf[(size_t)(e0 + r) * 64 + c];
    }
    if (tid < 128) b1s[tid] = b1[tid];
    if (tid < 64) { gs[tid] = gamma[tid]; bs[tid] = beta[tid]; }

    // ---------------- feats gather (one edge per thread, tid<128) ----------
    if (tid < 128) {
        const int e = e0 + tid;
        const int di = ei[e];            // dst = res[edge_index[0]]
        const int si = ei[E + e];        // src = res[edge_index[1]]
        const float* sr = res + (size_t)si * 56;
        const float* dr = res + (size_t)di * 56;
        const float s0 = esh[e * 4 + 0];
        const float sx = esh[e * 4 + 1];
        const float sy = esh[e * 4 + 2];
        const float sz = esh[e * 4 + 3];
        float* fr = fs + tid * F_STR;
        #pragma unroll
        for (int j = 0; j < 32; j++) { fr[j] = sr[j] * s0; fr[32 + j] = dr[j] * s0; }
        const float inv3 = 0.57735026918962576f;   // 1/sqrt(3)
        #pragma unroll
        for (int m = 0; m < 8; m++) {
            fr[64 + m] = (sr[32 + 3*m] * sx + sr[33 + 3*m] * sy + sr[34 + 3*m] * sz) * inv3;
            fr[72 + m] = (dr[32 + 3*m] * sx + dr[33 + 3*m] * sy + dr[34 + 3*m] * sz) * inv3;
        }
    }
    __syncthreads();

    // ---------------- phase 1: H = relu(X @ W1 + b1), rounded to tf32 ------
    // Permuted column layout for LDS.64 A loads:  col(k) = (k&3)*34 + (k>>2)
    {
        const int e    = tid >> 1;
        const int half = tid & 1;
        float* hrow = Hs + e * H_STR;
        #pragma unroll 1
        for (int jb = 0; jb < 2; jb++) {
            const int j0 = half * 64 + jb * 32;
            float acc[32];
            #pragma unroll
            for (int jj = 0; jj < 32; jj++) acc[jj] = b1s[j0 + jj];
            #pragma unroll 4
            for (int i = 0; i < 64; i++) {
                const float xv = Xs[e * 65 + i];
                const float* wrow = W1s + i * 128 + j0;
                #pragma unroll
                for (int jj = 0; jj < 32; jj++) acc[jj] = fmaf(xv, wrow[jj], acc[jj]);
            }
            #pragma unroll
            for (int jj = 0; jj < 32; jj++) {
                const int j = j0 + jj;
                hrow[(j & 3) * 34 + (j >> 2)] =
                    __uint_as_float(cvt_tf32(fmaxf(acc[jj], 0.f)));
            }
        }
    }
    if (tid < 128) {   // augmented column (b2) + K-padding, permuted slots
        float* hrow = Hs + tid * H_STR;
        hrow[32] = 1.0f;                            // k=128
        hrow[33] = 0.f; hrow[66] = 0.f; hrow[67] = 0.f;
        hrow[100] = 0.f; hrow[101] = 0.f; hrow[134] = 0.f; hrow[135] = 0.f;
    }
    __syncthreads();   // Xs / W1s dead from here; W2 buffers take over

    // zero K-padding rows (129..135) of both W2 chunk buffers
    for (int idx = tid; idx < 7 * W2_STR * 2; idx += 256) {
        int bsel = idx / (7 * W2_STR);
        int rr   = idx % (7 * W2_STR);
        W2s0[bsel * W2_SZ + 129 * W2_STR + rr] = 0.f;
    }

    // ---------------- main loop: 80 d-chunks of (pre-rounded) W2 -----------
    auto prefetch = [&](int d, int buf) {
        float* dstb = W2s0 + buf * W2_SZ;
        const float* src_base = w2r + (size_t)d * 64;
        #pragma unroll 8
        for (int c = tid; c < 128 * 16; c += 256) {
            int k = c >> 4, seg = c & 15;
            cp_async16(dstb + k * W2_STR + seg * 4, src_base + (size_t)k * 5120 + seg * 4);
        }
        if (tid < 16) cp_async16(dstb + 128 * W2_STR + tid * 4, b2r + (size_t)d * 64 + tid * 4);
        asm volatile("cp.async.commit_group;");
    };

    prefetch(0, 0);

    float acc[2][8][4];
    #pragma unroll
    for (int mt = 0; mt < 2; mt++)
        #pragma unroll
        for (int nt = 0; nt < 8; nt++)
            #pragma unroll
            for (int i = 0; i < 4; i++) acc[mt][nt][i] = 0.f;

    const int rowA0    = wp * 32 + g;       // a0/a2 row of m-tile 0
    const int kt_begin = kh ? 9 : 0;
    const int kt_end   = kh ? 17 : 9;

    const float* hb0 = Hs + (rowA0)      * H_STR + q * 34;
    const float* hb1 = Hs + (rowA0 + 8)  * H_STR + q * 34;
    const float* hb2 = Hs + (rowA0 + 16) * H_STR + q * 34;
    const float* hb3 = Hs + (rowA0 + 24) * H_STR + q * 34;

    #pragma unroll 1
    for (int d = 0; d < 80; d++) {
        const int buf = d & 1;
        if (d + 1 < 80) {
            prefetch(d + 1, buf ^ 1);
            asm volatile("cp.async.wait_group 1;");
        } else {
            asm volatile("cp.async.wait_group 0;");
        }
        __syncthreads();

        const float* Wb = W2s0 + buf * W2_SZ;
        const float f00 = fs[(rowA0)      * F_STR + d];
        const float f01 = fs[(rowA0 + 8)  * F_STR + d];
        const float f10 = fs[(rowA0 + 16) * F_STR + d];
        const float f11 = fs[(rowA0 + 24) * F_STR + d];

        #pragma unroll 3
        for (int kt = kt_begin; kt < kt_end; kt++) {
            const int k0 = kt * 8 + q;
            // A: one LDS.64 per row pair (k0, k0+4) thanks to permuted layout
            const float2 ha0 = *(const float2*)(hb0 + 2 * kt);
            const float2 ha1 = *(const float2*)(hb1 + 2 * kt);
            const float2 ha2 = *(const float2*)(hb2 + 2 * kt);
            const float2 ha3 = *(const float2*)(hb3 + 2 * kt);
            unsigned a0[4], a1[4];
            a0[0] = __float_as_uint(ha0.x * f00); a0[2] = __float_as_uint(ha0.y * f00);
            a0[1] = __float_as_uint(ha1.x * f01); a0[3] = __float_as_uint(ha1.y * f01);
            a1[0] = __float_as_uint(ha2.x * f10); a1[2] = __float_as_uint(ha2.y * f10);
            a1[1] = __float_as_uint(ha3.x * f11); a1[3] = __float_as_uint(ha3.y * f11);
            const float* wk0 = Wb + (size_t)k0 * W2_STR;        // b0 rows (k)
            const float* wk1 = Wb + (size_t)(k0 + 4) * W2_STR;  // b1 rows (k+4)
            #pragma unroll
            for (int nt = 0; nt < 8; nt++) {
                unsigned b[2];
                b[0] = __float_as_uint(wk0[nt * 8 + g]);
                b[1] = __float_as_uint(wk1[nt * 8 + g]);
                mma_tf32(acc[0][nt], a0, b);
                mma_tf32(acc[1][nt], a1, b);
            }
        }
        __syncthreads();   // protect buf^1 before next prefetch overwrites it
    }

    // ---------------- cross-warp (kt-split) accumulator reduction ----------
    float* red = W2s0;                       // W2 buffers are dead now
    if (kh == 1) {
        float* dst = red + wp * 2048;
        #pragma unroll
        for (int mt = 0; mt < 2; mt++)
            #pragma unroll
            for (int nt = 0; nt < 8; nt++)
                #pragma unroll
                for (int i = 0; i < 4; i++)
                    dst[(mt * 32 + nt * 4 + i) * 32 + lane] = acc[mt][nt][i];
    }
    __syncthreads();
    if (kh == 0) {
        const float* srcp = red + wp * 2048;
        #pragma unroll
        for (int mt = 0; mt < 2; mt++)
            #pragma unroll
            for (int nt = 0; nt < 8; nt++)
                #pragma unroll
                for (int i = 0; i < 4; i++)
                    acc[mt][nt][i] += srcp[(mt * 32 + nt * 4 + i) * 32 + lane];

        // ---------------- epilogue: residual + LayerNorm -------------------
        const float inv_s80 = 0.111803398874989485f;   // 1/sqrt(80)
        #pragma unroll
        for (int mt = 0; mt < 2; mt++) {
            #pragma unroll
            for (int par = 0; par < 2; par++) {
                const int r = rowA0 + mt * 16 + par * 8;
                const size_t rg = (size_t)(e0 + r);
                const float* xrow = xf + rg * 64;
                float v[16];
                float s = 0.f, ss = 0.f;
                #pragma unroll
                for (int nt = 0; nt < 8; nt++) {
                    const int h = nt * 8 + 2 * q;
                    const float2 xv = *(const float2*)(xrow + h);
                    const float v0 = acc[mt][nt][par * 2 + 0] * inv_s80 + xv.x;
                    const float v1 = acc[mt][nt][par * 2 + 1] * inv_s80 + xv.y;
                    v[nt * 2] = v0; v[nt * 2 + 1] = v1;
                    s += v0 + v1;
                    ss += v0 * v0 + v1 * v1;
                }
                s  += __shfl_xor_sync(0xffffffffu, s, 1);
                s  += __shfl_xor_sync(0xffffffffu, s, 2);
                ss += __shfl_xor_sync(0xffffffffu, ss, 1);
                ss += __shfl_xor_sync(0xffffffffu, ss, 2);
                const float mean = s * (1.f / 64.f);
                const float var  = ss * (1.f / 64.f) - mean * mean;
                const float rstd = rsqrtf(var + 1e-5f);
                float* orow = out + rg * 64;
                #pragma unroll
                for (int nt = 0; nt < 8; nt++) {
                    const int h = nt * 8 + 2 * q;
                    float2 o;
                    o.x = (v[nt * 2]     - mean) * rstd * gs[h]     + bs[h];
                    o.y = (v[nt * 2 + 1] - mean) * rstd * gs[h + 1] + bs[h + 1];
                    *(float2*)(orow + h) = o;
                }
            }
        }
    }
}

extern "C" void kernel_launch(void* const* d_in, const int* in_sizes, int n_in,
                              void* d_out, int out_size)
{
    const float* res   = (const float*)d_in[0];
    const float* xf    = (const float*)d_in[1];
    const float* esh   = (const float*)d_in[2];
    const float* W1    = (const float*)d_in[3];
    const float* b1    = (const float*)d_in[4];
    const float* W2    = (const float*)d_in[5];
    const float* b2    = (const float*)d_in[6];
    const float* gamma = (const float*)d_in[7];
    const float* beta  = (const float*)d_in[8];
    const int*   ei    = (const int*)d_in[9];   // int32: JAX x64-disabled

    const int E = in_sizes[1] / 64;            // edge_features is (E, 64)
    const size_t smem_bytes = SMEM_FLOATS * sizeof(float);

    cudaFuncSetAttribute(edge_kernel, cudaFuncAttributeMaxDynamicSharedMemorySize,
                         (int)smem_bytes);

    round_w2<<<(128 * 5120 + 255) / 256, 256>>>(W2, b2);
    edge_kernel<<<E / 128, 256, smem_bytes>>>(res, xf, esh, W1, b1,
                                              gamma, beta, ei, (float*)d_out, E);
}